// round 7
// baseline (speedup 1.0000x reference)
#include <cuda_runtime.h>

#define NS 200000
#define NA 400000
#define NU 200000
#define HH 64
#define ESS 2000000
#define EAS 4000000
#define EUS 2000000
#define NB 196                 // ceil(NS/1024) scan blocks
#define GEMM_TILES 3125        // NS/64
// smem: Xs2 (4164 ull, skewed, duplicated) + Ws (16384 f) + bias (64 f)
#define XS2_ULL 4164
#define GEMM_SMEM (XS2_ULL*8 + 16384*4 + 64*4)

typedef unsigned long long ull;

// ---------------- static device scratch (no allocations allowed) ----------------
__device__ __align__(256) float g_agg_ss[NS*HH];
__device__ __align__(256) float g_agg_as[NS*HH];
__device__ __align__(256) float g_agg_us[NS*HH];
__device__ __align__(256) float g_sub0[NS*HH];
__device__ __align__(256) float g_sub1[NS*HH];
__device__ int g_csr_ss[ESS];
__device__ int g_csr_as[EAS];
__device__ int g_csr_us[EUS];
__device__ int g_off_ss[NS+1];
__device__ int g_off_as[NS+1];
__device__ int g_off_us[NS+1];
__device__ int g_cur_ss[NS];
__device__ int g_cur_as[NS];
__device__ int g_cur_us[NS];
__device__ int g_part[3*256];
__device__ __align__(16) float g_W[3*4*HH*HH];   // [layer][r][k][o], r: 0=Wl_ss 1=Wl_as 2=Wl_us 3=Wr_sum
__device__ float g_bias[3*HH];

// ---------------- helpers ----------------
__device__ __forceinline__ int* rel_cur(int rel){ return rel==0? g_cur_ss : rel==1? g_cur_as : g_cur_us; }
__device__ __forceinline__ int* rel_off(int rel){ return rel==0? g_off_ss : rel==1? g_off_as : g_off_us; }
__device__ __forceinline__ int* rel_csr(int rel){ return rel==0? g_csr_ss : rel==1? g_csr_as : g_csr_us; }

// ---------------- init: transpose weights + fold Wr/bias sums + zero cursors ----------------
__global__ void k_init(const float* __restrict__ Wl, const float* __restrict__ bl,
                       const float* __restrict__ Wr)
{
    for (int idx = blockIdx.x*blockDim.x + threadIdx.x; idx < 3*4*64*64; idx += gridDim.x*blockDim.x){
        int o = idx & 63;
        int k = (idx>>6) & 63;
        int r = (idx>>12) & 3;
        int l = idx>>14;
        float w;
        if (r < 3) w = Wl[(((size_t)l*3 + r)*64 + o)*64 + k];
        else       w = Wr[(((size_t)l*3 + 0)*64 + o)*64 + k]
                     + Wr[(((size_t)l*3 + 1)*64 + o)*64 + k]
                     + Wr[(((size_t)l*3 + 2)*64 + o)*64 + k];
        g_W[idx] = w;
        if (idx < 3*64){
            int l2 = idx>>6, o2 = idx&63;
            g_bias[idx] = bl[(l2*3+0)*64+o2] + bl[(l2*3+1)*64+o2] + bl[(l2*3+2)*64+o2];
        }
    }
    for (int i = blockIdx.x*blockDim.x + threadIdx.x; i < NS; i += gridDim.x*blockDim.x){
        g_cur_ss[i]=0; g_cur_as[i]=0; g_cur_us[i]=0;
    }
}

// ---------------- merged CSR count: all 3 relations in one launch ----------------
// blocks [0,1024)=ss, [1024,3072)=as, [3072,4096)=us
__global__ void k_count_all(const int* __restrict__ d_ss, const int* __restrict__ d_as,
                            const int* __restrict__ d_us)
{
    int b = blockIdx.x;
    const int* dst; int E, b0, nb; int* cur;
    if (b < 1024){ dst=d_ss; E=ESS; b0=0;    nb=1024; cur=g_cur_ss; }
    else if (b < 3072){ dst=d_as; E=EAS; b0=1024; nb=2048; cur=g_cur_as; }
    else { dst=d_us; E=EUS; b0=3072; nb=1024; cur=g_cur_us; }
    for (int e = (b-b0)*blockDim.x + threadIdx.x; e < E; e += nb*blockDim.x)
        atomicAdd(&cur[__ldg(&dst[e])], 1);
}

// ---------------- merged scans (3 relations: blockIdx ranges) ----------------
__global__ void k_scan_local_all()
{
    int rel = blockIdx.x / NB;
    int blk = blockIdx.x % NB;
    const int* deg = rel_cur(rel);
    int* off = rel_off(rel);
    int* part = g_part + rel*256;
    __shared__ int s[2][1024];
    int t = threadIdx.x;
    int i = blk*1024 + t;
    int v = (i < NS) ? deg[i] : 0;
    int pa = 0;
    s[0][t] = v;
    __syncthreads();
    #pragma unroll
    for (int d = 1; d < 1024; d <<= 1){
        int val = s[pa][t];
        if (t >= d) val += s[pa][t-d];
        s[pa^1][t] = val;
        pa ^= 1;
        __syncthreads();
    }
    int inc = s[pa][t];
    if (i < NS) off[i] = inc - v;        // block-local exclusive
    if (t == 1023) part[blk] = inc;
}

// parallel scan of the NB=196 partials (one block per relation)
__global__ void k_scan_part_all()
{
    int rel = blockIdx.x;
    int* part = g_part + rel*256;
    int* off = rel_off(rel);
    __shared__ int ws[8];
    int t = threadIdx.x;
    int lane = t & 31, wid = t >> 5;
    int v = (t < NB) ? part[t] : 0;
    int x = v;
    #pragma unroll
    for (int d = 1; d < 32; d <<= 1){
        int y = __shfl_up_sync(0xffffffffu, x, d);
        if (lane >= d) x += y;
    }
    if (lane == 31) ws[wid] = x;
    __syncthreads();
    if (t == 0){
        int run = 0;
        #pragma unroll
        for (int i = 0; i < 8; i++){ int tmp = ws[i]; ws[i] = run; run += tmp; }
    }
    __syncthreads();
    x += ws[wid];
    if (t < NB) part[t] = x - v;         // exclusive partials
    if (t == 255) off[NS] = x;           // grand total
}

__global__ void k_scan_add_all()
{
    int rel = blockIdx.x / NB;
    int blk = blockIdx.x % NB;
    int* off = rel_off(rel);
    int* cur = rel_cur(rel);
    const int* part = g_part + rel*256;
    int i = blk*1024 + threadIdx.x;
    if (i < NS){
        int v = off[i] + part[blk];
        off[i] = v;
        cur[i] = v;       // cursor for fill
    }
}

// ---------------- merged fill ----------------
__global__ void k_fill_all(const int* __restrict__ ss_s, const int* __restrict__ ss_d,
                           const int* __restrict__ as_s, const int* __restrict__ as_d,
                           const int* __restrict__ us_s, const int* __restrict__ us_d)
{
    int b = blockIdx.x;
    const int* src; const int* dst; int E, b0, nb; int* cur; int* csr;
    if (b < 1024){ src=ss_s; dst=ss_d; E=ESS; b0=0;    nb=1024; cur=g_cur_ss; csr=g_csr_ss; }
    else if (b < 3072){ src=as_s; dst=as_d; E=EAS; b0=1024; nb=2048; cur=g_cur_as; csr=g_csr_as; }
    else { src=us_s; dst=us_d; E=EUS; b0=3072; nb=1024; cur=g_cur_us; csr=g_csr_us; }
    for (int e = (b-b0)*blockDim.x + threadIdx.x; e < E; e += nb*blockDim.x){
        int d = __ldg(&dst[e]);
        int p = atomicAdd(&cur[d], 1);
        csr[p] = __ldg(&src[e]);
    }
}

// ---------------- gather core (sum, 4-way unrolled) ----------------
__device__ __forceinline__ void gather_sum(const float2* __restrict__ x2,
                                           const int* __restrict__ csr,
                                           int b, int e, int lane,
                                           float& ax, float& ay)
{
    int i = b;
    for (; i + 4 <= e; i += 4){
        int s0 = __ldg(&csr[i]);
        int s1 = __ldg(&csr[i+1]);
        int s2 = __ldg(&csr[i+2]);
        int s3 = __ldg(&csr[i+3]);
        float2 v0 = __ldg(&x2[(size_t)s0*32 + lane]);
        float2 v1 = __ldg(&x2[(size_t)s1*32 + lane]);
        float2 v2 = __ldg(&x2[(size_t)s2*32 + lane]);
        float2 v3 = __ldg(&x2[(size_t)s3*32 + lane]);
        ax += (v0.x + v1.x) + (v2.x + v3.x);
        ay += (v0.y + v1.y) + (v2.y + v3.y);
    }
    for (; i < e; i++){
        int s0 = __ldg(&csr[i]);
        float2 v0 = __ldg(&x2[(size_t)s0*32 + lane]);
        ax += v0.x; ay += v0.y;
    }
}

// merged independent gathers: ss layer-0 (sum) + as (sum) + us (sum), one launch
__global__ void k_gather3(const float* __restrict__ xs, const float* __restrict__ xa,
                          const float* __restrict__ xu)
{
    int warp = (blockIdx.x*blockDim.x + threadIdx.x) >> 5;
    int lane = threadIdx.x & 31;
    const float2* x2; const int* csr; const int* off; float2* op; int node;
    if (warp < NS){
        node = warp; x2 = (const float2*)xs; csr = g_csr_ss; off = g_off_ss; op = (float2*)g_agg_ss;
    } else if (warp < 2*NS){
        node = warp - NS; x2 = (const float2*)xa; csr = g_csr_as; off = g_off_as; op = (float2*)g_agg_as;
    } else if (warp < 3*NS){
        node = warp - 2*NS; x2 = (const float2*)xu; csr = g_csr_us; off = g_off_us; op = (float2*)g_agg_us;
    } else return;
    int b = __ldg(&off[node]);
    int e = __ldg(&off[node+1]);
    float ax = 0.f, ay = 0.f;
    gather_sum(x2, csr, b, e, lane, ax, ay);
    op[(size_t)node*32 + lane] = make_float2(ax, ay);
}

// per-layer ss gather with mean (layers 1,2)
__global__ void k_gather_ss(int insel)
{
    const float* x = insel==1 ? g_sub0 : g_sub1;
    int warp = (blockIdx.x*blockDim.x + threadIdx.x) >> 5;
    int lane = threadIdx.x & 31;
    if (warp >= NS) return;
    int b = __ldg(&g_off_ss[warp]);
    int e = __ldg(&g_off_ss[warp+1]);
    float ax = 0.f, ay = 0.f;
    gather_sum((const float2*)x, g_csr_ss, b, e, lane, ax, ay);
    if (e > b){ float sc = 1.f/(float)(e-b); ax *= sc; ay *= sc; }
    ((float2*)g_agg_ss)[(size_t)warp*32 + lane] = make_float2(ax, ay);
}

// ---------------- fused layer GEMM: out = relu([agg_ss|agg_as|agg_us|sub] @ Wcat + b) ----------------
// Xs2 stores x duplicated {x,x} per 8-byte word, skewed by node>>4 to dodge bank conflicts.
#define XI(node, k) ((node)*65 + ((node)>>4) + (k))

__global__ void __launch_bounds__(256,2)
k_gemm(const float* __restrict__ sub_ext, int sub_sel, int out_sel, int layer)
{
    extern __shared__ ull sm8[];
    ull*   Xs2 = sm8;                         // XS2_ULL
    float* Ws  = (float*)(sm8 + XS2_ULL);     // 4*64*64
    float* Bs  = Ws + 16384;                  // 64

    const int tid = threadIdx.x;
    const int tx = tid & 15;           // output group: outs tx*4..tx*4+3
    const int ty = tid >> 4;           // node group:  nodes ty + 16*mi

    for (int j = tid; j < 16384; j += 256) Ws[j] = g_W[layer*16384 + j];
    if (tid < 64) Bs[tid] = g_bias[layer*64 + tid];

    const float* Asub = sub_sel==0 ? sub_ext : (sub_sel==1 ? g_sub0 : g_sub1);
    float* outp = out_sel==0 ? g_sub0 : g_sub1;

    for (int tile = blockIdx.x; tile < GEMM_TILES; tile += gridDim.x){
        const int base = tile*64;
        ull acc[4][2];
        #pragma unroll
        for (int mi = 0; mi < 4; mi++){ acc[mi][0] = 0ull; acc[mi][1] = 0ull; }

        #pragma unroll
        for (int r = 0; r < 4; r++){
            const float* A = (r==0) ? g_agg_ss : (r==1) ? g_agg_as : (r==2) ? g_agg_us : Asub;
            __syncthreads();   // protect Xs2 from previous k-loop readers (also covers Ws init)
            #pragma unroll
            for (int j = tid; j < 1024; j += 256){
                int node = j >> 4, c = j & 15;
                float4 v = *(const float4*)(A + ((size_t)(base+node))*64 + c*4);
                ull* d = &Xs2[XI(node, c*4)];
                ull p0, p1, p2, p3;
                asm("mov.b64 %0, {%1, %1};" : "=l"(p0) : "f"(v.x));
                asm("mov.b64 %0, {%1, %1};" : "=l"(p1) : "f"(v.y));
                asm("mov.b64 %0, {%1, %1};" : "=l"(p2) : "f"(v.z));
                asm("mov.b64 %0, {%1, %1};" : "=l"(p3) : "f"(v.w));
                d[0]=p0; d[1]=p1; d[2]=p2; d[3]=p3;
            }
            __syncthreads();
            const float* wr = Ws + r*4096 + tx*4;
            const ull* xr0 = Xs2 + XI(ty,      0);
            const ull* xr1 = Xs2 + XI(ty+16,   0);
            const ull* xr2 = Xs2 + XI(ty+32,   0);
            const ull* xr3 = Xs2 + XI(ty+48,   0);
            #pragma unroll 16
            for (int k = 0; k < 64; k++){
                const ull* wp = (const ull*)(wr + k*64);
                ull wa = wp[0], wb = wp[1];
                ull xv;
                xv = xr0[k];
                asm("fma.rn.f32x2 %0, %1, %2, %0;" : "+l"(acc[0][0]) : "l"(xv), "l"(wa));
                asm("fma.rn.f32x2 %0, %1, %2, %0;" : "+l"(acc[0][1]) : "l"(xv), "l"(wb));
                xv = xr1[k];
                asm("fma.rn.f32x2 %0, %1, %2, %0;" : "+l"(acc[1][0]) : "l"(xv), "l"(wa));
                asm("fma.rn.f32x2 %0, %1, %2, %0;" : "+l"(acc[1][1]) : "l"(xv), "l"(wb));
                xv = xr2[k];
                asm("fma.rn.f32x2 %0, %1, %2, %0;" : "+l"(acc[2][0]) : "l"(xv), "l"(wa));
                asm("fma.rn.f32x2 %0, %1, %2, %0;" : "+l"(acc[2][1]) : "l"(xv), "l"(wb));
                xv = xr3[k];
                asm("fma.rn.f32x2 %0, %1, %2, %0;" : "+l"(acc[3][0]) : "l"(xv), "l"(wa));
                asm("fma.rn.f32x2 %0, %1, %2, %0;" : "+l"(acc[3][1]) : "l"(xv), "l"(wb));
            }
        }
        float b0 = Bs[tx*4+0], b1 = Bs[tx*4+1], b2 = Bs[tx*4+2], b3 = Bs[tx*4+3];
        #pragma unroll
        for (int mi = 0; mi < 4; mi++){
            float x0,x1,x2,x3;
            asm("mov.b64 {%0, %1}, %2;" : "=f"(x0), "=f"(x1) : "l"(acc[mi][0]));
            asm("mov.b64 {%0, %1}, %2;" : "=f"(x2), "=f"(x3) : "l"(acc[mi][1]));
            float4 o;
            o.x = fmaxf(x0 + b0, 0.f);
            o.y = fmaxf(x1 + b1, 0.f);
            o.z = fmaxf(x2 + b2, 0.f);
            o.w = fmaxf(x3 + b3, 0.f);
            *(float4*)(outp + ((size_t)(base + ty + 16*mi))*64 + tx*4) = o;
        }
    }
}

// ---------------- head: softmax(sub @ Wf.T + bf) ----------------
__global__ void k_head(const float* __restrict__ Wf, const float* __restrict__ bf,
                       float* __restrict__ out, int sub_sel)
{
    const float* sub = sub_sel==1 ? g_sub0 : g_sub1;
    int warp = (blockIdx.x*blockDim.x + threadIdx.x) >> 5;
    int lane = threadIdx.x & 31;
    if (warp >= NS) return;
    float2 xv = *(const float2*)(sub + (size_t)warp*64 + lane*2);
    float p[6];
    #pragma unroll
    for (int o = 0; o < 6; o++){
        float w0 = __ldg(&Wf[o*64 + lane*2]);
        float w1 = __ldg(&Wf[o*64 + lane*2 + 1]);
        p[o] = xv.x*w0 + xv.y*w1;
    }
    #pragma unroll
    for (int s = 16; s; s >>= 1){
        #pragma unroll
        for (int o = 0; o < 6; o++) p[o] += __shfl_xor_sync(0xffffffffu, p[o], s);
    }
    float m = -1e30f;
    #pragma unroll
    for (int o = 0; o < 6; o++){ p[o] += __ldg(&bf[o]); m = fmaxf(m, p[o]); }
    float s = 0.f;
    #pragma unroll
    for (int o = 0; o < 6; o++){ p[o] = expf(p[o] - m); s += p[o]; }
    float inv = 1.f/s;
    if (lane == 0){
        #pragma unroll
        for (int o = 0; o < 6; o++) out[(size_t)warp*6 + o] = p[o]*inv;
    }
}

// ---------------- launch ----------------
extern "C" void kernel_launch(void* const* d_in, const int* in_sizes, int n_in,
                              void* d_out, int out_size)
{
    const float* x_sub   = (const float*)d_in[0];
    const float* x_agr   = (const float*)d_in[1];
    const float* x_urb   = (const float*)d_in[2];
    const float* Wl      = (const float*)d_in[3];
    const float* bl      = (const float*)d_in[4];
    const float* Wr      = (const float*)d_in[5];
    const float* Wf      = (const float*)d_in[6];
    const float* bf      = (const float*)d_in[7];
    const int*   e_ss    = (const int*)d_in[8];
    const int*   e_as_s  = (const int*)d_in[9];
    const int*   e_as_d  = (const int*)d_in[10];
    const int*   e_us    = (const int*)d_in[11];
    float* out = (float*)d_out;

    cudaFuncSetAttribute(k_gemm, cudaFuncAttributeMaxDynamicSharedMemorySize, GEMM_SMEM);

    k_init<<<512,256>>>(Wl, bl, Wr);

    k_count_all<<<4096,256>>>(e_ss + ESS, e_as_d, e_us + EUS);

    k_scan_local_all<<<3*NB,1024>>>();
    k_scan_part_all<<<3,256>>>();
    k_scan_add_all<<<3*NB,1024>>>();

    k_fill_all<<<4096,256>>>(e_ss, e_ss + ESS, e_as_s, e_as_d, e_us, e_us + EUS);

    // all layer-invariant + layer-0 aggregations in one concurrent launch
    k_gather3<<<75000,256>>>(x_sub, x_agr, x_urb);

    // layer 0: sum aggregation, sub input = x_sub, out -> g_sub0
    k_gemm<<<296,256,GEMM_SMEM>>>(x_sub, 0, 0, 0);
    // layer 1: mean aggregation, sub input = g_sub0, out -> g_sub1
    k_gather_ss<<<25000,256>>>(1);
    k_gemm<<<296,256,GEMM_SMEM>>>(nullptr, 1, 1, 1);
    // layer 2: mean aggregation, sub input = g_sub1, out -> g_sub0
    k_gather_ss<<<25000,256>>>(2);
    k_gemm<<<296,256,GEMM_SMEM>>>(nullptr, 2, 0, 2);

    k_head<<<25000,256>>>(Wf, bf, out, 1);
}

// round 8
// speedup vs baseline: 1.0168x; 1.0168x over previous
#include <cuda_runtime.h>

#define NS 200000
#define NA 400000
#define NU 200000
#define HH 64
#define ESS 2000000
#define EAS 4000000
#define EUS 2000000
#define NB 196                 // ceil(NS/1024) scan blocks
#define GEMM_TILES 3125        // NS/64
#define XS2_ULL 4164
// smem: Xs2 (ull) + Ws 16384f + Bs 64f + Wfs 384f + bfs 8f
#define GEMM_SMEM (XS2_ULL*8 + (16384 + 64 + 384 + 8)*4)

typedef unsigned long long ull;

// ---------------- static device scratch (no allocations allowed) ----------------
__device__ __align__(256) float g_agg_ss[NS*HH];
__device__ __align__(256) float g_agg_as[NS*HH];
__device__ __align__(256) float g_agg_us[NS*HH];
__device__ __align__(256) float g_sub0[NS*HH];
__device__ __align__(256) float g_sub1[NS*HH];
__device__ int g_csr_ss[ESS];
__device__ int g_csr_as[EAS];
__device__ int g_csr_us[EUS];
__device__ int g_off_ss[NS+1];
__device__ int g_off_as[NS+1];
__device__ int g_off_us[NS+1];
__device__ int g_cur_ss[NS];
__device__ int g_cur_as[NS];
__device__ int g_cur_us[NS];
__device__ int g_part[3*256];
__device__ __align__(16) float g_W[3*4*HH*HH];   // [layer][r][k][o]
__device__ float g_bias[3*HH];

// ---------------- helpers ----------------
__device__ __forceinline__ int* rel_cur(int rel){ return rel==0? g_cur_ss : rel==1? g_cur_as : g_cur_us; }
__device__ __forceinline__ int* rel_off(int rel){ return rel==0? g_off_ss : rel==1? g_off_as : g_off_us; }
__device__ __forceinline__ int* rel_csr(int rel){ return rel==0? g_csr_ss : rel==1? g_csr_as : g_csr_us; }

// ---------------- init: transpose weights + fold Wr/bias sums + zero cursors ----------------
__global__ void k_init(const float* __restrict__ Wl, const float* __restrict__ bl,
                       const float* __restrict__ Wr)
{
    for (int idx = blockIdx.x*blockDim.x + threadIdx.x; idx < 3*4*64*64; idx += gridDim.x*blockDim.x){
        int o = idx & 63;
        int k = (idx>>6) & 63;
        int r = (idx>>12) & 3;
        int l = idx>>14;
        float w;
        if (r < 3) w = Wl[(((size_t)l*3 + r)*64 + o)*64 + k];
        else       w = Wr[(((size_t)l*3 + 0)*64 + o)*64 + k]
                     + Wr[(((size_t)l*3 + 1)*64 + o)*64 + k]
                     + Wr[(((size_t)l*3 + 2)*64 + o)*64 + k];
        g_W[idx] = w;
        if (idx < 3*64){
            int l2 = idx>>6, o2 = idx&63;
            g_bias[idx] = bl[(l2*3+0)*64+o2] + bl[(l2*3+1)*64+o2] + bl[(l2*3+2)*64+o2];
        }
    }
    for (int i = blockIdx.x*blockDim.x + threadIdx.x; i < NS; i += gridDim.x*blockDim.x){
        g_cur_ss[i]=0; g_cur_as[i]=0; g_cur_us[i]=0;
    }
}

// ---------------- merged CSR count: blocks [0,2048)=ss [2048,6144)=as [6144,8192)=us ----------------
__global__ void k_count_all(const int* __restrict__ d_ss, const int* __restrict__ d_as,
                            const int* __restrict__ d_us)
{
    int b = blockIdx.x;
    const int* dst; int E, b0, nb; int* cur;
    if (b < 2048){ dst=d_ss; E=ESS; b0=0;    nb=2048; cur=g_cur_ss; }
    else if (b < 6144){ dst=d_as; E=EAS; b0=2048; nb=4096; cur=g_cur_as; }
    else { dst=d_us; E=EUS; b0=6144; nb=2048; cur=g_cur_us; }
    for (int e = (b-b0)*blockDim.x + threadIdx.x; e < E; e += nb*blockDim.x)
        atomicAdd(&cur[__ldg(&dst[e])], 1);
}

// ---------------- merged scans ----------------
__global__ void k_scan_local_all()
{
    int rel = blockIdx.x / NB;
    int blk = blockIdx.x % NB;
    const int* deg = rel_cur(rel);
    int* off = rel_off(rel);
    int* part = g_part + rel*256;
    __shared__ int s[2][1024];
    int t = threadIdx.x;
    int i = blk*1024 + t;
    int v = (i < NS) ? deg[i] : 0;
    int pa = 0;
    s[0][t] = v;
    __syncthreads();
    #pragma unroll
    for (int d = 1; d < 1024; d <<= 1){
        int val = s[pa][t];
        if (t >= d) val += s[pa][t-d];
        s[pa^1][t] = val;
        pa ^= 1;
        __syncthreads();
    }
    int inc = s[pa][t];
    if (i < NS) off[i] = inc - v;        // block-local exclusive
    if (t == 1023) part[blk] = inc;
}

// parallel scan of the NB=196 partials (one block per relation)
__global__ void k_scan_part_all()
{
    int rel = blockIdx.x;
    int* part = g_part + rel*256;
    int* off = rel_off(rel);
    __shared__ int ws[8];
    int t = threadIdx.x;
    int lane = t & 31, wid = t >> 5;
    int v = (t < NB) ? part[t] : 0;
    int x = v;
    #pragma unroll
    for (int d = 1; d < 32; d <<= 1){
        int y = __shfl_up_sync(0xffffffffu, x, d);
        if (lane >= d) x += y;
    }
    if (lane == 31) ws[wid] = x;
    __syncthreads();
    if (t == 0){
        int run = 0;
        #pragma unroll
        for (int i = 0; i < 8; i++){ int tmp = ws[i]; ws[i] = run; run += tmp; }
    }
    __syncthreads();
    x += ws[wid];
    if (t < NB) part[t] = x - v;         // exclusive partials
    if (t == 255) off[NS] = x;           // grand total
}

__global__ void k_scan_add_all()
{
    int rel = blockIdx.x / NB;
    int blk = blockIdx.x % NB;
    int* off = rel_off(rel);
    int* cur = rel_cur(rel);
    const int* part = g_part + rel*256;
    int i = blk*1024 + threadIdx.x;
    if (i < NS){
        int v = off[i] + part[blk];
        off[i] = v;
        cur[i] = v;       // cursor for fill
    }
}

// ---------------- merged fill ----------------
__global__ void k_fill_all(const int* __restrict__ ss_s, const int* __restrict__ ss_d,
                           const int* __restrict__ as_s, const int* __restrict__ as_d,
                           const int* __restrict__ us_s, const int* __restrict__ us_d)
{
    int b = blockIdx.x;
    const int* src; const int* dst; int E, b0, nb; int* cur; int* csr;
    if (b < 2048){ src=ss_s; dst=ss_d; E=ESS; b0=0;    nb=2048; cur=g_cur_ss; csr=g_csr_ss; }
    else if (b < 6144){ src=as_s; dst=as_d; E=EAS; b0=2048; nb=4096; cur=g_cur_as; csr=g_csr_as; }
    else { src=us_s; dst=us_d; E=EUS; b0=6144; nb=2048; cur=g_cur_us; csr=g_csr_us; }
    for (int e = (b-b0)*blockDim.x + threadIdx.x; e < E; e += nb*blockDim.x){
        int d = __ldg(&dst[e]);
        int p = atomicAdd(&cur[d], 1);
        csr[p] = __ldg(&src[e]);
    }
}

// ---------------- gather core (sum, 4-way unrolled) ----------------
__device__ __forceinline__ void gather_sum(const float2* __restrict__ x2,
                                           const int* __restrict__ csr,
                                           int b, int e, int lane,
                                           float& ax, float& ay)
{
    int i = b;
    for (; i + 4 <= e; i += 4){
        int s0 = __ldg(&csr[i]);
        int s1 = __ldg(&csr[i+1]);
        int s2 = __ldg(&csr[i+2]);
        int s3 = __ldg(&csr[i+3]);
        float2 v0 = __ldg(&x2[(size_t)s0*32 + lane]);
        float2 v1 = __ldg(&x2[(size_t)s1*32 + lane]);
        float2 v2 = __ldg(&x2[(size_t)s2*32 + lane]);
        float2 v3 = __ldg(&x2[(size_t)s3*32 + lane]);
        ax += (v0.x + v1.x) + (v2.x + v3.x);
        ay += (v0.y + v1.y) + (v2.y + v3.y);
    }
    for (; i < e; i++){
        int s0 = __ldg(&csr[i]);
        float2 v0 = __ldg(&x2[(size_t)s0*32 + lane]);
        ax += v0.x; ay += v0.y;
    }
}

// external-feature gather (sum): one warp per destination node; one relation per launch
__global__ void k_gather_ext(const float* __restrict__ x, int rel, int outsel)
{
    int warp = (blockIdx.x*blockDim.x + threadIdx.x) >> 5;
    int lane = threadIdx.x & 31;
    if (warp >= NS) return;
    const int* csr = rel_csr(rel);
    const int* off = rel_off(rel);
    float* op = outsel==0 ? g_agg_ss : (outsel==1 ? g_agg_as : g_agg_us);
    int b = __ldg(&off[warp]);
    int e = __ldg(&off[warp+1]);
    float ax = 0.f, ay = 0.f;
    gather_sum((const float2*)x, csr, b, e, lane, ax, ay);
    ((float2*)op)[(size_t)warp*32 + lane] = make_float2(ax, ay);
}

// per-layer ss gather with mean (layers 1,2)
__global__ void k_gather_ss(int insel)
{
    const float* x = insel==1 ? g_sub0 : g_sub1;
    int warp = (blockIdx.x*blockDim.x + threadIdx.x) >> 5;
    int lane = threadIdx.x & 31;
    if (warp >= NS) return;
    int b = __ldg(&g_off_ss[warp]);
    int e = __ldg(&g_off_ss[warp+1]);
    float ax = 0.f, ay = 0.f;
    gather_sum((const float2*)x, g_csr_ss, b, e, lane, ax, ay);
    if (e > b){ float sc = 1.f/(float)(e-b); ax *= sc; ay *= sc; }
    ((float2*)g_agg_ss)[(size_t)warp*32 + lane] = make_float2(ax, ay);
}

// ---------------- fused layer GEMM (+ optional softmax head epilogue) ----------------
// Xs2 stores x duplicated {x,x} per 8-byte word, skewed by node>>4 to dodge bank conflicts.
#define XI(node, k) ((node)*65 + ((node)>>4) + (k))

__global__ void __launch_bounds__(256,2)
k_gemm(const float* __restrict__ sub_ext, int sub_sel, int out_sel, int layer,
       const float* __restrict__ Wf, const float* __restrict__ bf,
       float* __restrict__ outhead, int do_head)
{
    extern __shared__ ull sm8[];
    ull*   Xs2 = sm8;                         // XS2_ULL
    float* Ws  = (float*)(sm8 + XS2_ULL);     // 16384
    float* Bs  = Ws + 16384;                  // 64
    float* Wfs = Bs + 64;                     // 384
    float* bfs = Wfs + 384;                   // 8

    const int tid = threadIdx.x;
    const int tx = tid & 15;           // output group: outs tx*4..tx*4+3
    const int ty = tid >> 4;           // node group:  nodes ty + 16*mi

    for (int j = tid; j < 16384; j += 256) Ws[j] = g_W[layer*16384 + j];
    if (tid < 64) Bs[tid] = g_bias[layer*64 + tid];
    if (do_head){
        for (int j = tid; j < 384; j += 256) Wfs[j] = Wf[j];
        if (tid < 6) bfs[tid] = bf[tid];
    }

    const float* Asub = sub_sel==0 ? sub_ext : (sub_sel==1 ? g_sub0 : g_sub1);
    float* outp = out_sel==0 ? g_sub0 : g_sub1;

    for (int tile = blockIdx.x; tile < GEMM_TILES; tile += gridDim.x){
        const int base = tile*64;
        ull acc[4][2];
        #pragma unroll
        for (int mi = 0; mi < 4; mi++){ acc[mi][0] = 0ull; acc[mi][1] = 0ull; }

        #pragma unroll
        for (int r = 0; r < 4; r++){
            const float* A = (r==0) ? g_agg_ss : (r==1) ? g_agg_as : (r==2) ? g_agg_us : Asub;
            __syncthreads();   // protect Xs2 from previous readers (also covers Ws/Wfs init)
            #pragma unroll
            for (int j = tid; j < 1024; j += 256){
                int node = j >> 4, c = j & 15;
                float4 v = *(const float4*)(A + ((size_t)(base+node))*64 + c*4);
                ull* d = &Xs2[XI(node, c*4)];
                ull p0, p1, p2, p3;
                asm("mov.b64 %0, {%1, %1};" : "=l"(p0) : "f"(v.x));
                asm("mov.b64 %0, {%1, %1};" : "=l"(p1) : "f"(v.y));
                asm("mov.b64 %0, {%1, %1};" : "=l"(p2) : "f"(v.z));
                asm("mov.b64 %0, {%1, %1};" : "=l"(p3) : "f"(v.w));
                d[0]=p0; d[1]=p1; d[2]=p2; d[3]=p3;
            }
            __syncthreads();
            const float* wr = Ws + r*4096 + tx*4;
            const ull* xr0 = Xs2 + XI(ty,      0);
            const ull* xr1 = Xs2 + XI(ty+16,   0);
            const ull* xr2 = Xs2 + XI(ty+32,   0);
            const ull* xr3 = Xs2 + XI(ty+48,   0);
            #pragma unroll 16
            for (int k = 0; k < 64; k++){
                const ull* wp = (const ull*)(wr + k*64);
                ull wa = wp[0], wb = wp[1];
                ull xv;
                xv = xr0[k];
                asm("fma.rn.f32x2 %0, %1, %2, %0;" : "+l"(acc[0][0]) : "l"(xv), "l"(wa));
                asm("fma.rn.f32x2 %0, %1, %2, %0;" : "+l"(acc[0][1]) : "l"(xv), "l"(wb));
                xv = xr1[k];
                asm("fma.rn.f32x2 %0, %1, %2, %0;" : "+l"(acc[1][0]) : "l"(xv), "l"(wa));
                asm("fma.rn.f32x2 %0, %1, %2, %0;" : "+l"(acc[1][1]) : "l"(xv), "l"(wb));
                xv = xr2[k];
                asm("fma.rn.f32x2 %0, %1, %2, %0;" : "+l"(acc[2][0]) : "l"(xv), "l"(wa));
                asm("fma.rn.f32x2 %0, %1, %2, %0;" : "+l"(acc[2][1]) : "l"(xv), "l"(wb));
                xv = xr3[k];
                asm("fma.rn.f32x2 %0, %1, %2, %0;" : "+l"(acc[3][0]) : "l"(xv), "l"(wa));
                asm("fma.rn.f32x2 %0, %1, %2, %0;" : "+l"(acc[3][1]) : "l"(xv), "l"(wb));
            }
        }
        float b0 = Bs[tx*4+0], b1 = Bs[tx*4+1], b2 = Bs[tx*4+2], b3 = Bs[tx*4+3];
        if (!do_head){
            #pragma unroll
            for (int mi = 0; mi < 4; mi++){
                float x0,x1,x2,x3;
                asm("mov.b64 {%0, %1}, %2;" : "=f"(x0), "=f"(x1) : "l"(acc[mi][0]));
                asm("mov.b64 {%0, %1}, %2;" : "=f"(x2), "=f"(x3) : "l"(acc[mi][1]));
                float4 o;
                o.x = fmaxf(x0 + b0, 0.f);
                o.y = fmaxf(x1 + b1, 0.f);
                o.z = fmaxf(x2 + b2, 0.f);
                o.w = fmaxf(x3 + b3, 0.f);
                *(float4*)(outp + ((size_t)(base + ty + 16*mi))*64 + tx*4) = o;
            }
        } else {
            // fused head: relu -> smem -> dot Wf -> softmax -> d_out
            float* Hs = (float*)sm8;           // 64 nodes x stride 68
            __syncthreads();                   // k-loop readers done before overwriting Xs2
            #pragma unroll
            for (int mi = 0; mi < 4; mi++){
                float x0,x1,x2,x3;
                asm("mov.b64 {%0, %1}, %2;" : "=f"(x0), "=f"(x1) : "l"(acc[mi][0]));
                asm("mov.b64 {%0, %1}, %2;" : "=f"(x2), "=f"(x3) : "l"(acc[mi][1]));
                float4 o;
                o.x = fmaxf(x0 + b0, 0.f);
                o.y = fmaxf(x1 + b1, 0.f);
                o.z = fmaxf(x2 + b2, 0.f);
                o.w = fmaxf(x3 + b3, 0.f);
                *(float4*)(Hs + (ty + 16*mi)*68 + tx*4) = o;
            }
            __syncthreads();
            int node = tid >> 2, q = tid & 3;  // 4 threads per node, 16 k each
            const float* hrow = Hs + node*68 + q*16;
            float p[6];
            #pragma unroll
            for (int o = 0; o < 6; o++) p[o] = 0.f;
            #pragma unroll
            for (int k = 0; k < 16; k++){
                float xv = hrow[k];
                #pragma unroll
                for (int o = 0; o < 6; o++) p[o] += xv * Wfs[o*64 + q*16 + k];
            }
            #pragma unroll
            for (int s = 1; s < 4; s <<= 1){
                #pragma unroll
                for (int o = 0; o < 6; o++) p[o] += __shfl_xor_sync(0xffffffffu, p[o], s);
            }
            if (q == 0){
                float m = -1e30f;
                #pragma unroll
                for (int o = 0; o < 6; o++){ p[o] += bfs[o]; m = fmaxf(m, p[o]); }
                float ssum = 0.f;
                #pragma unroll
                for (int o = 0; o < 6; o++){ p[o] = expf(p[o] - m); ssum += p[o]; }
                float inv = 1.f/ssum;
                float* op = outhead + (size_t)(base + node)*6;
                #pragma unroll
                for (int o = 0; o < 6; o++) op[o] = p[o]*inv;
            }
            // next tile's r-loop starts with __syncthreads(), protecting Hs
        }
    }
}

// ---------------- launch ----------------
extern "C" void kernel_launch(void* const* d_in, const int* in_sizes, int n_in,
                              void* d_out, int out_size)
{
    const float* x_sub   = (const float*)d_in[0];
    const float* x_agr   = (const float*)d_in[1];
    const float* x_urb   = (const float*)d_in[2];
    const float* Wl      = (const float*)d_in[3];
    const float* bl      = (const float*)d_in[4];
    const float* Wr      = (const float*)d_in[5];
    const float* Wf      = (const float*)d_in[6];
    const float* bf      = (const float*)d_in[7];
    const int*   e_ss    = (const int*)d_in[8];
    const int*   e_as_s  = (const int*)d_in[9];
    const int*   e_as_d  = (const int*)d_in[10];
    const int*   e_us    = (const int*)d_in[11];
    float* out = (float*)d_out;

    cudaFuncSetAttribute(k_gemm, cudaFuncAttributeMaxDynamicSharedMemorySize, GEMM_SMEM);

    k_init<<<512,256>>>(Wl, bl, Wr);

    k_count_all<<<8192,256>>>(e_ss + ESS, e_as_d, e_us + EUS);

    k_scan_local_all<<<3*NB,1024>>>();
    k_scan_part_all<<<3,256>>>();
    k_scan_add_all<<<3*NB,1024>>>();

    k_fill_all<<<8192,256>>>(e_ss, e_ss + ESS, e_as_s, e_as_d, e_us, e_us + EUS);

    // layer-invariant aggregations, separate launches for L2 locality
    k_gather_ext<<<25000,256>>>(x_agr, 1, 1);
    k_gather_ext<<<25000,256>>>(x_urb, 2, 2);

    // layer 0: sum aggregation, sub input = x_sub, out -> g_sub0
    k_gather_ext<<<25000,256>>>(x_sub, 0, 0);
    k_gemm<<<296,256,GEMM_SMEM>>>(x_sub, 0, 0, 0, nullptr, nullptr, nullptr, 0);
    // layer 1: mean aggregation, sub input = g_sub0, out -> g_sub1
    k_gather_ss<<<25000,256>>>(1);
    k_gemm<<<296,256,GEMM_SMEM>>>(nullptr, 1, 1, 1, nullptr, nullptr, nullptr, 0);
    // layer 2: mean aggregation, sub input = g_sub1, head fused -> d_out
    k_gather_ss<<<25000,256>>>(2);
    k_gemm<<<296,256,GEMM_SMEM>>>(nullptr, 2, 0, 2, Wf, bf, out, 1);
}

// round 9
// speedup vs baseline: 1.0333x; 1.0162x over previous
#include <cuda_runtime.h>
#include <cuda_fp16.h>

#define NS 200000
#define NA 400000
#define NU 200000
#define HH 64
#define ESS 2000000
#define EAS 4000000
#define EUS 2000000
#define NB 196                 // ceil(NS/1024) scan blocks
#define GEMM_TILES 3125        // NS/64
#define XS2_ULL 4164
// smem: Xs2 (ull) + Ws 16384f + Bs 64f + Wfs 384f + bfs 8f
#define GEMM_SMEM (XS2_ULL*8 + (16384 + 64 + 384 + 8)*4)

typedef unsigned long long ull;

// ---------------- static device scratch (no allocations allowed) ----------------
__device__ __align__(256) __half h_sub[NS*HH];
__device__ __align__(256) __half h_agr[NA*HH];
__device__ __align__(256) __half h_urb[NU*HH];
__device__ __align__(256) __half g_agg_ss[NS*HH];
__device__ __align__(256) __half g_agg_as[NS*HH];
__device__ __align__(256) __half g_agg_us[NS*HH];
__device__ __align__(256) __half g_sub0[NS*HH];
__device__ __align__(256) __half g_sub1[NS*HH];
__device__ int g_csr_ss[ESS];
__device__ int g_csr_as[EAS];
__device__ int g_csr_us[EUS];
__device__ int g_off_ss[NS+1];
__device__ int g_off_as[NS+1];
__device__ int g_off_us[NS+1];
__device__ int g_cur_ss[NS];
__device__ int g_cur_as[NS];
__device__ int g_cur_us[NS];
__device__ int g_part[3*256];
__device__ __align__(16) float g_W[3*4*HH*HH];   // [layer][r][k][o]
__device__ float g_bias[3*HH];

// ---------------- helpers ----------------
__device__ __forceinline__ int* rel_cur(int rel){ return rel==0? g_cur_ss : rel==1? g_cur_as : g_cur_us; }
__device__ __forceinline__ int* rel_off(int rel){ return rel==0? g_off_ss : rel==1? g_off_as : g_off_us; }
__device__ __forceinline__ int* rel_csr(int rel){ return rel==0? g_csr_ss : rel==1? g_csr_as : g_csr_us; }

// ---------------- init: transpose weights + fold Wr/bias sums + zero cursors ----------------
__global__ void k_init(const float* __restrict__ Wl, const float* __restrict__ bl,
                       const float* __restrict__ Wr)
{
    for (int idx = blockIdx.x*blockDim.x + threadIdx.x; idx < 3*4*64*64; idx += gridDim.x*blockDim.x){
        int o = idx & 63;
        int k = (idx>>6) & 63;
        int r = (idx>>12) & 3;
        int l = idx>>14;
        float w;
        if (r < 3) w = Wl[(((size_t)l*3 + r)*64 + o)*64 + k];
        else       w = Wr[(((size_t)l*3 + 0)*64 + o)*64 + k]
                     + Wr[(((size_t)l*3 + 1)*64 + o)*64 + k]
                     + Wr[(((size_t)l*3 + 2)*64 + o)*64 + k];
        g_W[idx] = w;
        if (idx < 3*64){
            int l2 = idx>>6, o2 = idx&63;
            g_bias[idx] = bl[(l2*3+0)*64+o2] + bl[(l2*3+1)*64+o2] + bl[(l2*3+2)*64+o2];
        }
    }
    for (int i = blockIdx.x*blockDim.x + threadIdx.x; i < NS; i += gridDim.x*blockDim.x){
        g_cur_ss[i]=0; g_cur_as[i]=0; g_cur_us[i]=0;
    }
}

// ---------------- fp32 -> fp16 conversion of node features ----------------
// blocks [0,2048)=sub [2048,6144)=agr [6144,8192)=urb
__global__ void k_convert(const float* __restrict__ xs, const float* __restrict__ xa,
                          const float* __restrict__ xu)
{
    int b = blockIdx.x;
    const float4* src; uint2* dst; int n4, b0, nb;
    if (b < 2048){ src=(const float4*)xs; dst=(uint2*)h_sub; n4=NS*16; b0=0;    nb=2048; }
    else if (b < 6144){ src=(const float4*)xa; dst=(uint2*)h_agr; n4=NA*16; b0=2048; nb=4096; }
    else { src=(const float4*)xu; dst=(uint2*)h_urb; n4=NU*16; b0=6144; nb=2048; }
    for (int i = (b-b0)*blockDim.x + threadIdx.x; i < n4; i += nb*blockDim.x){
        float4 v = __ldg(&src[i]);
        __half2 h0 = __floats2half2_rn(v.x, v.y);
        __half2 h1 = __floats2half2_rn(v.z, v.w);
        uint2 u;
        u.x = *(unsigned*)&h0;
        u.y = *(unsigned*)&h1;
        dst[i] = u;
    }
}

// ---------------- merged CSR count: blocks [0,2048)=ss [2048,6144)=as [6144,8192)=us ----------------
__global__ void k_count_all(const int* __restrict__ d_ss, const int* __restrict__ d_as,
                            const int* __restrict__ d_us)
{
    int b = blockIdx.x;
    const int* dst; int E, b0, nb; int* cur;
    if (b < 2048){ dst=d_ss; E=ESS; b0=0;    nb=2048; cur=g_cur_ss; }
    else if (b < 6144){ dst=d_as; E=EAS; b0=2048; nb=4096; cur=g_cur_as; }
    else { dst=d_us; E=EUS; b0=6144; nb=2048; cur=g_cur_us; }
    for (int e = (b-b0)*blockDim.x + threadIdx.x; e < E; e += nb*blockDim.x)
        atomicAdd(&cur[__ldg(&dst[e])], 1);
}

// ---------------- merged scans ----------------
__global__ void k_scan_local_all()
{
    int rel = blockIdx.x / NB;
    int blk = blockIdx.x % NB;
    const int* deg = rel_cur(rel);
    int* off = rel_off(rel);
    int* part = g_part + rel*256;
    __shared__ int s[2][1024];
    int t = threadIdx.x;
    int i = blk*1024 + t;
    int v = (i < NS) ? deg[i] : 0;
    int pa = 0;
    s[0][t] = v;
    __syncthreads();
    #pragma unroll
    for (int d = 1; d < 1024; d <<= 1){
        int val = s[pa][t];
        if (t >= d) val += s[pa][t-d];
        s[pa^1][t] = val;
        pa ^= 1;
        __syncthreads();
    }
    int inc = s[pa][t];
    if (i < NS) off[i] = inc - v;        // block-local exclusive
    if (t == 1023) part[blk] = inc;
}

// parallel scan of the NB=196 partials (one block per relation)
__global__ void k_scan_part_all()
{
    int rel = blockIdx.x;
    int* part = g_part + rel*256;
    int* off = rel_off(rel);
    __shared__ int ws[8];
    int t = threadIdx.x;
    int lane = t & 31, wid = t >> 5;
    int v = (t < NB) ? part[t] : 0;
    int x = v;
    #pragma unroll
    for (int d = 1; d < 32; d <<= 1){
        int y = __shfl_up_sync(0xffffffffu, x, d);
        if (lane >= d) x += y;
    }
    if (lane == 31) ws[wid] = x;
    __syncthreads();
    if (t == 0){
        int run = 0;
        #pragma unroll
        for (int i = 0; i < 8; i++){ int tmp = ws[i]; ws[i] = run; run += tmp; }
    }
    __syncthreads();
    x += ws[wid];
    if (t < NB) part[t] = x - v;         // exclusive partials
    if (t == 255) off[NS] = x;           // grand total
}

__global__ void k_scan_add_all()
{
    int rel = blockIdx.x / NB;
    int blk = blockIdx.x % NB;
    int* off = rel_off(rel);
    int* cur = rel_cur(rel);
    const int* part = g_part + rel*256;
    int i = blk*1024 + threadIdx.x;
    if (i < NS){
        int v = off[i] + part[blk];
        off[i] = v;
        cur[i] = v;       // cursor for fill
    }
}

// ---------------- merged fill ----------------
__global__ void k_fill_all(const int* __restrict__ ss_s, const int* __restrict__ ss_d,
                           const int* __restrict__ as_s, const int* __restrict__ as_d,
                           const int* __restrict__ us_s, const int* __restrict__ us_d)
{
    int b = blockIdx.x;
    const int* src; const int* dst; int E, b0, nb; int* cur; int* csr;
    if (b < 2048){ src=ss_s; dst=ss_d; E=ESS; b0=0;    nb=2048; cur=g_cur_ss; csr=g_csr_ss; }
    else if (b < 6144){ src=as_s; dst=as_d; E=EAS; b0=2048; nb=4096; cur=g_cur_as; csr=g_csr_as; }
    else { src=us_s; dst=us_d; E=EUS; b0=6144; nb=2048; cur=g_cur_us; csr=g_csr_us; }
    for (int e = (b-b0)*blockDim.x + threadIdx.x; e < E; e += nb*blockDim.x){
        int d = __ldg(&dst[e]);
        int p = atomicAdd(&cur[d], 1);
        csr[p] = __ldg(&src[e]);
    }
}

// ---------------- gather core (fp16 rows, fp32 accumulate, 4-way unrolled) ----------------
__device__ __forceinline__ void gather_sum_h(const __half2* __restrict__ x2,
                                             const int* __restrict__ csr,
                                             int b, int e, int lane,
                                             float& ax, float& ay)
{
    int i = b;
    for (; i + 4 <= e; i += 4){
        int s0 = __ldg(&csr[i]);
        int s1 = __ldg(&csr[i+1]);
        int s2 = __ldg(&csr[i+2]);
        int s3 = __ldg(&csr[i+3]);
        float2 f0 = __half22float2(__ldg(&x2[(size_t)s0*32 + lane]));
        float2 f1 = __half22float2(__ldg(&x2[(size_t)s1*32 + lane]));
        float2 f2 = __half22float2(__ldg(&x2[(size_t)s2*32 + lane]));
        float2 f3 = __half22float2(__ldg(&x2[(size_t)s3*32 + lane]));
        ax += (f0.x + f1.x) + (f2.x + f3.x);
        ay += (f0.y + f1.y) + (f2.y + f3.y);
    }
    for (; i < e; i++){
        int s0 = __ldg(&csr[i]);
        float2 f0 = __half22float2(__ldg(&x2[(size_t)s0*32 + lane]));
        ax += f0.x; ay += f0.y;
    }
}

// external-feature gather (sum): one warp per destination node; one relation per launch
__global__ void k_gather_ext(int rel, int outsel)
{
    int warp = (blockIdx.x*blockDim.x + threadIdx.x) >> 5;
    int lane = threadIdx.x & 31;
    if (warp >= NS) return;
    const __half* x = rel==0 ? h_sub : (rel==1 ? h_agr : h_urb);
    const int* csr = rel_csr(rel);
    const int* off = rel_off(rel);
    __half* op = outsel==0 ? g_agg_ss : (outsel==1 ? g_agg_as : g_agg_us);
    int b = __ldg(&off[warp]);
    int e = __ldg(&off[warp+1]);
    float ax = 0.f, ay = 0.f;
    gather_sum_h((const __half2*)x, csr, b, e, lane, ax, ay);
    ((__half2*)op)[(size_t)warp*32 + lane] = __floats2half2_rn(ax, ay);
}

// per-layer ss gather with mean (layers 1,2)
__global__ void k_gather_ss(int insel)
{
    const __half* x = insel==1 ? g_sub0 : g_sub1;
    int warp = (blockIdx.x*blockDim.x + threadIdx.x) >> 5;
    int lane = threadIdx.x & 31;
    if (warp >= NS) return;
    int b = __ldg(&g_off_ss[warp]);
    int e = __ldg(&g_off_ss[warp+1]);
    float ax = 0.f, ay = 0.f;
    gather_sum_h((const __half2*)x, g_csr_ss, b, e, lane, ax, ay);
    if (e > b){ float sc = 1.f/(float)(e-b); ax *= sc; ay *= sc; }
    ((__half2*)g_agg_ss)[(size_t)warp*32 + lane] = __floats2half2_rn(ax, ay);
}

// ---------------- fused layer GEMM (+ optional softmax head epilogue) ----------------
// Xs2 stores x duplicated {x,x} per 8-byte word, skewed by node>>4 to dodge bank conflicts.
#define XI(node, k) ((node)*65 + ((node)>>4) + (k))

__global__ void __launch_bounds__(256,2)
k_gemm(int sub_sel, int out_sel, int layer,
       const float* __restrict__ Wf, const float* __restrict__ bf,
       float* __restrict__ outhead, int do_head)
{
    extern __shared__ ull sm8[];
    ull*   Xs2 = sm8;                         // XS2_ULL
    float* Ws  = (float*)(sm8 + XS2_ULL);     // 16384
    float* Bs  = Ws + 16384;                  // 64
    float* Wfs = Bs + 64;                     // 384
    float* bfs = Wfs + 384;                   // 8

    const int tid = threadIdx.x;
    const int tx = tid & 15;           // output group: outs tx*4..tx*4+3
    const int ty = tid >> 4;           // node group:  nodes ty + 16*mi

    for (int j = tid; j < 16384; j += 256) Ws[j] = g_W[layer*16384 + j];
    if (tid < 64) Bs[tid] = g_bias[layer*64 + tid];
    if (do_head){
        for (int j = tid; j < 384; j += 256) Wfs[j] = Wf[j];
        if (tid < 6) bfs[tid] = bf[tid];
    }

    const __half* Asub = sub_sel==0 ? h_sub : (sub_sel==1 ? g_sub0 : g_sub1);
    __half* outp = out_sel==0 ? g_sub0 : g_sub1;

    for (int tile = blockIdx.x; tile < GEMM_TILES; tile += gridDim.x){
        const int base = tile*64;
        ull acc[4][2];
        #pragma unroll
        for (int mi = 0; mi < 4; mi++){ acc[mi][0] = 0ull; acc[mi][1] = 0ull; }

        #pragma unroll
        for (int r = 0; r < 4; r++){
            const __half* A = (r==0) ? g_agg_ss : (r==1) ? g_agg_as : (r==2) ? g_agg_us : Asub;
            __syncthreads();   // protect Xs2 from previous readers (also covers Ws/Wfs init)
            #pragma unroll
            for (int j = tid; j < 1024; j += 256){
                int node = j >> 4, c = j & 15;
                uint2 u = *(const uint2*)(A + ((size_t)(base+node))*64 + c*4);
                float2 f0 = __half22float2(*(__half2*)&u.x);
                float2 f1 = __half22float2(*(__half2*)&u.y);
                ull* d = &Xs2[XI(node, c*4)];
                ull p0, p1, p2, p3;
                asm("mov.b64 %0, {%1, %1};" : "=l"(p0) : "f"(f0.x));
                asm("mov.b64 %0, {%1, %1};" : "=l"(p1) : "f"(f0.y));
                asm("mov.b64 %0, {%1, %1};" : "=l"(p2) : "f"(f1.x));
                asm("mov.b64 %0, {%1, %1};" : "=l"(p3) : "f"(f1.y));
                d[0]=p0; d[1]=p1; d[2]=p2; d[3]=p3;
            }
            __syncthreads();
            const float* wr = Ws + r*4096 + tx*4;
            const ull* xr0 = Xs2 + XI(ty,      0);
            const ull* xr1 = Xs2 + XI(ty+16,   0);
            const ull* xr2 = Xs2 + XI(ty+32,   0);
            const ull* xr3 = Xs2 + XI(ty+48,   0);
            #pragma unroll 16
            for (int k = 0; k < 64; k++){
                const ull* wp = (const ull*)(wr + k*64);
                ull wa = wp[0], wb = wp[1];
                ull xv;
                xv = xr0[k];
                asm("fma.rn.f32x2 %0, %1, %2, %0;" : "+l"(acc[0][0]) : "l"(xv), "l"(wa));
                asm("fma.rn.f32x2 %0, %1, %2, %0;" : "+l"(acc[0][1]) : "l"(xv), "l"(wb));
                xv = xr1[k];
                asm("fma.rn.f32x2 %0, %1, %2, %0;" : "+l"(acc[1][0]) : "l"(xv), "l"(wa));
                asm("fma.rn.f32x2 %0, %1, %2, %0;" : "+l"(acc[1][1]) : "l"(xv), "l"(wb));
                xv = xr2[k];
                asm("fma.rn.f32x2 %0, %1, %2, %0;" : "+l"(acc[2][0]) : "l"(xv), "l"(wa));
                asm("fma.rn.f32x2 %0, %1, %2, %0;" : "+l"(acc[2][1]) : "l"(xv), "l"(wb));
                xv = xr3[k];
                asm("fma.rn.f32x2 %0, %1, %2, %0;" : "+l"(acc[3][0]) : "l"(xv), "l"(wa));
                asm("fma.rn.f32x2 %0, %1, %2, %0;" : "+l"(acc[3][1]) : "l"(xv), "l"(wb));
            }
        }
        float b0 = Bs[tx*4+0], b1 = Bs[tx*4+1], b2 = Bs[tx*4+2], b3 = Bs[tx*4+3];
        if (!do_head){
            #pragma unroll
            for (int mi = 0; mi < 4; mi++){
                float x0,x1,x2,x3;
                asm("mov.b64 {%0, %1}, %2;" : "=f"(x0), "=f"(x1) : "l"(acc[mi][0]));
                asm("mov.b64 {%0, %1}, %2;" : "=f"(x2), "=f"(x3) : "l"(acc[mi][1]));
                __half2 h0 = __floats2half2_rn(fmaxf(x0 + b0, 0.f), fmaxf(x1 + b1, 0.f));
                __half2 h1 = __floats2half2_rn(fmaxf(x2 + b2, 0.f), fmaxf(x3 + b3, 0.f));
                uint2 u;
                u.x = *(unsigned*)&h0;
                u.y = *(unsigned*)&h1;
                *(uint2*)(outp + ((size_t)(base + ty + 16*mi))*64 + tx*4) = u;
            }
        } else {
            // fused head: relu -> smem -> dot Wf -> softmax -> d_out
            float* Hs = (float*)sm8;           // 64 nodes x stride 68
            __syncthreads();                   // k-loop readers done before overwriting Xs2
            #pragma unroll
            for (int mi = 0; mi < 4; mi++){
                float x0,x1,x2,x3;
                asm("mov.b64 {%0, %1}, %2;" : "=f"(x0), "=f"(x1) : "l"(acc[mi][0]));
                asm("mov.b64 {%0, %1}, %2;" : "=f"(x2), "=f"(x3) : "l"(acc[mi][1]));
                float4 o;
                o.x = fmaxf(x0 + b0, 0.f);
                o.y = fmaxf(x1 + b1, 0.f);
                o.z = fmaxf(x2 + b2, 0.f);
                o.w = fmaxf(x3 + b3, 0.f);
                *(float4*)(Hs + (ty + 16*mi)*68 + tx*4) = o;
            }
            __syncthreads();
            int node = tid >> 2, q = tid & 3;  // 4 threads per node, 16 k each
            const float* hrow = Hs + node*68 + q*16;
            float p[6];
            #pragma unroll
            for (int o = 0; o < 6; o++) p[o] = 0.f;
            #pragma unroll
            for (int k = 0; k < 16; k++){
                float xv = hrow[k];
                #pragma unroll
                for (int o = 0; o < 6; o++) p[o] += xv * Wfs[o*64 + q*16 + k];
            }
            #pragma unroll
            for (int s = 1; s < 4; s <<= 1){
                #pragma unroll
                for (int o = 0; o < 6; o++) p[o] += __shfl_xor_sync(0xffffffffu, p[o], s);
            }
            if (q == 0){
                float m = -1e30f;
                #pragma unroll
                for (int o = 0; o < 6; o++){ p[o] += bfs[o]; m = fmaxf(m, p[o]); }
                float ssum = 0.f;
                #pragma unroll
                for (int o = 0; o < 6; o++){ p[o] = expf(p[o] - m); ssum += p[o]; }
                float inv = 1.f/ssum;
                float* op = outhead + (size_t)(base + node)*6;
                #pragma unroll
                for (int o = 0; o < 6; o++) op[o] = p[o]*inv;
            }
            // next tile's r-loop starts with __syncthreads(), protecting Hs
        }
    }
}

// ---------------- launch ----------------
extern "C" void kernel_launch(void* const* d_in, const int* in_sizes, int n_in,
                              void* d_out, int out_size)
{
    const float* x_sub   = (const float*)d_in[0];
    const float* x_agr   = (const float*)d_in[1];
    const float* x_urb   = (const float*)d_in[2];
    const float* Wl      = (const float*)d_in[3];
    const float* bl      = (const float*)d_in[4];
    const float* Wr      = (const float*)d_in[5];
    const float* Wf      = (const float*)d_in[6];
    const float* bf      = (const float*)d_in[7];
    const int*   e_ss    = (const int*)d_in[8];
    const int*   e_as_s  = (const int*)d_in[9];
    const int*   e_as_d  = (const int*)d_in[10];
    const int*   e_us    = (const int*)d_in[11];
    float* out = (float*)d_out;

    cudaFuncSetAttribute(k_gemm, cudaFuncAttributeMaxDynamicSharedMemorySize, GEMM_SMEM);

    k_init<<<512,256>>>(Wl, bl, Wr);
    k_convert<<<8192,256>>>(x_sub, x_agr, x_urb);

    k_count_all<<<8192,256>>>(e_ss + ESS, e_as_d, e_us + EUS);

    k_scan_local_all<<<3*NB,1024>>>();
    k_scan_part_all<<<3,256>>>();
    k_scan_add_all<<<3*NB,1024>>>();

    k_fill_all<<<8192,256>>>(e_ss, e_ss + ESS, e_as_s, e_as_d, e_us, e_us + EUS);

    // layer-invariant aggregations, separate launches for L2 locality
    k_gather_ext<<<25000,256>>>(1, 1);
    k_gather_ext<<<25000,256>>>(2, 2);

    // layer 0: sum aggregation, sub input = h_sub, out -> g_sub0
    k_gather_ext<<<25000,256>>>(0, 0);
    k_gemm<<<296,256,GEMM_SMEM>>>(0, 0, 0, nullptr, nullptr, nullptr, 0);
    // layer 1: mean aggregation, sub input = g_sub0, out -> g_sub1
    k_gather_ss<<<25000,256>>>(1);
    k_gemm<<<296,256,GEMM_SMEM>>>(1, 1, 1, nullptr, nullptr, nullptr, 0);
    // layer 2: mean aggregation, sub input = g_sub1, head fused -> d_out
    k_gather_ss<<<25000,256>>>(2);
    k_gemm<<<296,256,GEMM_SMEM>>>(2, 0, 2, Wf, bf, out, 1);
}

// round 10
// speedup vs baseline: 2.0702x; 2.0035x over previous
#include <cuda_runtime.h>
#include <cuda_fp16.h>
#include <cstdint>

#define NS 200000
#define NA 400000
#define NU 200000
#define HH 64
#define ESS 2000000
#define EAS 4000000
#define EUS 2000000
#define NB 196                 // ceil(NS/1024) scan blocks
#define GEMM_TILES 3125        // NS/64

// smem layout (bytes):
//   Ws  half[256][72]  36864   @ 0
//   As  half[256][72]  36864   @ 36864   (4 relations x 64 rows; aliased by Hs f32[64][68])
//   Bs  f32[64]          256   @ 73728
//   Wfs f32[384]        1536   @ 73984
//   bfs f32[8]            32   @ 75520
#define SMEM_WS   0
#define SMEM_AS   36864
#define SMEM_BS   73728
#define SMEM_WFS  73984
#define SMEM_BFS  75520
#define GEMM_SMEM 75552

typedef unsigned long long ull;

// ---------------- static device scratch (no allocations allowed) ----------------
__device__ __align__(256) __half h_sub[NS*HH];
__device__ __align__(256) __half h_agr[NA*HH];
__device__ __align__(256) __half h_urb[NU*HH];
__device__ __align__(256) __half g_agg_ss[NS*HH];
__device__ __align__(256) __half g_agg_as[NS*HH];
__device__ __align__(256) __half g_agg_us[NS*HH];
__device__ __align__(256) __half g_sub0[NS*HH];
__device__ __align__(256) __half g_sub1[NS*HH];
__device__ int g_csr_ss[ESS];
__device__ int g_csr_as[EAS];
__device__ int g_csr_us[EUS];
__device__ int g_off_ss[NS+1];
__device__ int g_off_as[NS+1];
__device__ int g_off_us[NS+1];
__device__ int g_cur_ss[NS];
__device__ int g_cur_as[NS];
__device__ int g_cur_us[NS];
__device__ int g_part[3*256];
__device__ __align__(16) __half g_Wh[3*4*HH*HH];   // [layer][r*64+k][o] fp16
__device__ float g_bias[3*HH];

// ---------------- helpers ----------------
__device__ __forceinline__ int* rel_cur(int rel){ return rel==0? g_cur_ss : rel==1? g_cur_as : g_cur_us; }
__device__ __forceinline__ int* rel_off(int rel){ return rel==0? g_off_ss : rel==1? g_off_as : g_off_us; }
__device__ __forceinline__ int* rel_csr(int rel){ return rel==0? g_csr_ss : rel==1? g_csr_as : g_csr_us; }

__device__ __forceinline__ void ldsm_x4(uint32_t& r0, uint32_t& r1, uint32_t& r2, uint32_t& r3, uint32_t addr){
    asm volatile("ldmatrix.sync.aligned.m8n8.x4.shared.b16 {%0,%1,%2,%3}, [%4];"
        : "=r"(r0),"=r"(r1),"=r"(r2),"=r"(r3) : "r"(addr));
}
__device__ __forceinline__ void ldsm_x4_t(uint32_t& r0, uint32_t& r1, uint32_t& r2, uint32_t& r3, uint32_t addr){
    asm volatile("ldmatrix.sync.aligned.m8n8.x4.trans.shared.b16 {%0,%1,%2,%3}, [%4];"
        : "=r"(r0),"=r"(r1),"=r"(r2),"=r"(r3) : "r"(addr));
}
__device__ __forceinline__ void mma16816(float* c, uint32_t a0,uint32_t a1,uint32_t a2,uint32_t a3,
                                         uint32_t b0, uint32_t b1){
    asm volatile("mma.sync.aligned.m16n8k16.row.col.f32.f16.f16.f32 "
                 "{%0,%1,%2,%3},{%4,%5,%6,%7},{%8,%9},{%0,%1,%2,%3};"
        : "+f"(c[0]),"+f"(c[1]),"+f"(c[2]),"+f"(c[3])
        : "r"(a0),"r"(a1),"r"(a2),"r"(a3),"r"(b0),"r"(b1));
}

// ---------------- init: build fp16 weights [layer][r*64+k][o] + fused bias + zero cursors ----------------
__global__ void k_init(const float* __restrict__ Wl, const float* __restrict__ bl,
                       const float* __restrict__ Wr)
{
    for (int idx = blockIdx.x*blockDim.x + threadIdx.x; idx < 3*4*64*64; idx += gridDim.x*blockDim.x){
        int o = idx & 63;
        int k = (idx>>6) & 63;
        int r = (idx>>12) & 3;
        int l = idx>>14;
        float w;
        if (r < 3) w = Wl[(((size_t)l*3 + r)*64 + o)*64 + k];
        else       w = Wr[(((size_t)l*3 + 0)*64 + o)*64 + k]
                     + Wr[(((size_t)l*3 + 1)*64 + o)*64 + k]
                     + Wr[(((size_t)l*3 + 2)*64 + o)*64 + k];
        g_Wh[idx] = __float2half(w);
        if (idx < 3*64){
            int l2 = idx>>6, o2 = idx&63;
            g_bias[idx] = bl[(l2*3+0)*64+o2] + bl[(l2*3+1)*64+o2] + bl[(l2*3+2)*64+o2];
        }
    }
    for (int i = blockIdx.x*blockDim.x + threadIdx.x; i < NS; i += gridDim.x*blockDim.x){
        g_cur_ss[i]=0; g_cur_as[i]=0; g_cur_us[i]=0;
    }
}

// ---------------- fp32 -> fp16 conversion of node features ----------------
__global__ void k_convert(const float* __restrict__ xs, const float* __restrict__ xa,
                          const float* __restrict__ xu)
{
    int b = blockIdx.x;
    const float4* src; uint2* dst; int n4, b0, nb;
    if (b < 2048){ src=(const float4*)xs; dst=(uint2*)h_sub; n4=NS*16; b0=0;    nb=2048; }
    else if (b < 6144){ src=(const float4*)xa; dst=(uint2*)h_agr; n4=NA*16; b0=2048; nb=4096; }
    else { src=(const float4*)xu; dst=(uint2*)h_urb; n4=NU*16; b0=6144; nb=2048; }
    for (int i = (b-b0)*blockDim.x + threadIdx.x; i < n4; i += nb*blockDim.x){
        float4 v = __ldg(&src[i]);
        __half2 h0 = __floats2half2_rn(v.x, v.y);
        __half2 h1 = __floats2half2_rn(v.z, v.w);
        uint2 u;
        u.x = *(unsigned*)&h0;
        u.y = *(unsigned*)&h1;
        dst[i] = u;
    }
}

// ---------------- merged CSR count ----------------
__global__ void k_count_all(const int* __restrict__ d_ss, const int* __restrict__ d_as,
                            const int* __restrict__ d_us)
{
    int b = blockIdx.x;
    const int* dst; int E, b0, nb; int* cur;
    if (b < 2048){ dst=d_ss; E=ESS; b0=0;    nb=2048; cur=g_cur_ss; }
    else if (b < 6144){ dst=d_as; E=EAS; b0=2048; nb=4096; cur=g_cur_as; }
    else { dst=d_us; E=EUS; b0=6144; nb=2048; cur=g_cur_us; }
    for (int e = (b-b0)*blockDim.x + threadIdx.x; e < E; e += nb*blockDim.x)
        atomicAdd(&cur[__ldg(&dst[e])], 1);
}

// ---------------- merged scans ----------------
__global__ void k_scan_local_all()
{
    int rel = blockIdx.x / NB;
    int blk = blockIdx.x % NB;
    const int* deg = rel_cur(rel);
    int* off = rel_off(rel);
    int* part = g_part + rel*256;
    __shared__ int s[2][1024];
    int t = threadIdx.x;
    int i = blk*1024 + t;
    int v = (i < NS) ? deg[i] : 0;
    int pa = 0;
    s[0][t] = v;
    __syncthreads();
    #pragma unroll
    for (int d = 1; d < 1024; d <<= 1){
        int val = s[pa][t];
        if (t >= d) val += s[pa][t-d];
        s[pa^1][t] = val;
        pa ^= 1;
        __syncthreads();
    }
    int inc = s[pa][t];
    if (i < NS) off[i] = inc - v;        // block-local exclusive
    if (t == 1023) part[blk] = inc;
}

__global__ void k_scan_part_all()
{
    int rel = blockIdx.x;
    int* part = g_part + rel*256;
    int* off = rel_off(rel);
    __shared__ int ws[8];
    int t = threadIdx.x;
    int lane = t & 31, wid = t >> 5;
    int v = (t < NB) ? part[t] : 0;
    int x = v;
    #pragma unroll
    for (int d = 1; d < 32; d <<= 1){
        int y = __shfl_up_sync(0xffffffffu, x, d);
        if (lane >= d) x += y;
    }
    if (lane == 31) ws[wid] = x;
    __syncthreads();
    if (t == 0){
        int run = 0;
        #pragma unroll
        for (int i = 0; i < 8; i++){ int tmp = ws[i]; ws[i] = run; run += tmp; }
    }
    __syncthreads();
    x += ws[wid];
    if (t < NB) part[t] = x - v;         // exclusive partials
    if (t == 255) off[NS] = x;           // grand total
}

__global__ void k_scan_add_all()
{
    int rel = blockIdx.x / NB;
    int blk = blockIdx.x % NB;
    int* off = rel_off(rel);
    int* cur = rel_cur(rel);
    const int* part = g_part + rel*256;
    int i = blk*1024 + threadIdx.x;
    if (i < NS){
        int v = off[i] + part[blk];
        off[i] = v;
        cur[i] = v;       // cursor for fill
    }
}

// ---------------- merged fill ----------------
__global__ void k_fill_all(const int* __restrict__ ss_s, const int* __restrict__ ss_d,
                           const int* __restrict__ as_s, const int* __restrict__ as_d,
                           const int* __restrict__ us_s, const int* __restrict__ us_d)
{
    int b = blockIdx.x;
    const int* src; const int* dst; int E, b0, nb; int* cur; int* csr;
    if (b < 2048){ src=ss_s; dst=ss_d; E=ESS; b0=0;    nb=2048; cur=g_cur_ss; csr=g_csr_ss; }
    else if (b < 6144){ src=as_s; dst=as_d; E=EAS; b0=2048; nb=4096; cur=g_cur_as; csr=g_csr_as; }
    else { src=us_s; dst=us_d; E=EUS; b0=6144; nb=2048; cur=g_cur_us; csr=g_csr_us; }
    for (int e = (b-b0)*blockDim.x + threadIdx.x; e < E; e += nb*blockDim.x){
        int d = __ldg(&dst[e]);
        int p = atomicAdd(&cur[d], 1);
        csr[p] = __ldg(&src[e]);
    }
}

// ---------------- gather core (fp16 rows, fp32 accumulate, 4-way unrolled) ----------------
__device__ __forceinline__ void gather_sum_h(const __half2* __restrict__ x2,
                                             const int* __restrict__ csr,
                                             int b, int e, int lane,
                                             float& ax, float& ay)
{
    int i = b;
    for (; i + 4 <= e; i += 4){
        int s0 = __ldg(&csr[i]);
        int s1 = __ldg(&csr[i+1]);
        int s2 = __ldg(&csr[i+2]);
        int s3 = __ldg(&csr[i+3]);
        float2 f0 = __half22float2(__ldg(&x2[(size_t)s0*32 + lane]));
        float2 f1 = __half22float2(__ldg(&x2[(size_t)s1*32 + lane]));
        float2 f2 = __half22float2(__ldg(&x2[(size_t)s2*32 + lane]));
        float2 f3 = __half22float2(__ldg(&x2[(size_t)s3*32 + lane]));
        ax += (f0.x + f1.x) + (f2.x + f3.x);
        ay += (f0.y + f1.y) + (f2.y + f3.y);
    }
    for (; i < e; i++){
        int s0 = __ldg(&csr[i]);
        float2 f0 = __half22float2(__ldg(&x2[(size_t)s0*32 + lane]));
        ax += f0.x; ay += f0.y;
    }
}

__global__ void k_gather_ext(int rel, int outsel)
{
    int warp = (blockIdx.x*blockDim.x + threadIdx.x) >> 5;
    int lane = threadIdx.x & 31;
    if (warp >= NS) return;
    const __half* x = rel==0 ? h_sub : (rel==1 ? h_agr : h_urb);
    const int* csr = rel_csr(rel);
    const int* off = rel_off(rel);
    __half* op = outsel==0 ? g_agg_ss : (outsel==1 ? g_agg_as : g_agg_us);
    int b = __ldg(&off[warp]);
    int e = __ldg(&off[warp+1]);
    float ax = 0.f, ay = 0.f;
    gather_sum_h((const __half2*)x, csr, b, e, lane, ax, ay);
    ((__half2*)op)[(size_t)warp*32 + lane] = __floats2half2_rn(ax, ay);
}

__global__ void k_gather_ss(int insel)
{
    const __half* x = insel==1 ? g_sub0 : g_sub1;
    int warp = (blockIdx.x*blockDim.x + threadIdx.x) >> 5;
    int lane = threadIdx.x & 31;
    if (warp >= NS) return;
    int b = __ldg(&g_off_ss[warp]);
    int e = __ldg(&g_off_ss[warp+1]);
    float ax = 0.f, ay = 0.f;
    gather_sum_h((const __half2*)x, g_csr_ss, b, e, lane, ax, ay);
    if (e > b){ float sc = 1.f/(float)(e-b); ax *= sc; ay *= sc; }
    ((__half2*)g_agg_ss)[(size_t)warp*32 + lane] = __floats2half2_rn(ax, ay);
}

// ---------------- fused layer GEMM on tensor cores (+ optional softmax head epilogue) ----------------
// C[64 nodes][64 outs] = relu( [agg_ss|agg_as|agg_us|sub] @ Wcat + bias )
// A staged As[r*64+m][72] halves (144B rows, ldmatrix conflict-free); W staged Ws[256][72].
__global__ void __launch_bounds__(256,2)
k_gemm(int sub_sel, int out_sel, int layer,
       const float* __restrict__ Wf, const float* __restrict__ bf,
       float* __restrict__ outhead, int do_head)
{
    extern __shared__ char sm[];
    __half* Ws  = (__half*)(sm + SMEM_WS);
    __half* As  = (__half*)(sm + SMEM_AS);
    float*  Bs  = (float*)(sm + SMEM_BS);
    float*  Wfs = (float*)(sm + SMEM_WFS);
    float*  bfs = (float*)(sm + SMEM_BFS);

    const int tid  = threadIdx.x;
    const int lane = tid & 31;
    const int warp = tid >> 5;
    const int wm   = warp & 3;          // m-block: rows wm*16..+15
    const int wn   = warp >> 2;         // n-block: cols wn*32..+31

    // stage weights (once): g_Wh[layer][row][o] -> Ws[row][72]
    {
        const __half* wsrc = g_Wh + layer*16384;
        #pragma unroll
        for (int it = 0; it < 8; it++){
            int chunk = it*256 + tid;           // 2048 chunks of 8 halves
            int row = chunk >> 3, c = chunk & 7;
            *(uint4*)(Ws + row*72 + c*8) = *(const uint4*)(wsrc + row*64 + c*8);
        }
    }
    if (tid < 64) Bs[tid] = g_bias[layer*64 + tid];
    if (do_head){
        for (int j = tid; j < 384; j += 256) Wfs[j] = Wf[j];
        if (tid < 6) bfs[tid] = bf[tid];
    }

    const __half* Asub = sub_sel==0 ? h_sub : (sub_sel==1 ? g_sub0 : g_sub1);
    __half* outp = out_sel==0 ? g_sub0 : g_sub1;

    // per-lane ldmatrix address components
    const int l8  = lane & 7;
    const int grp = lane >> 3;
    const int row_off = l8 + ((grp & 1) << 3);      // 0..15
    const int col_off = (grp & 2) << 2;             // 0 or 8
    const uint32_t as_base = (uint32_t)__cvta_generic_to_shared(As);
    const uint32_t ws_base = (uint32_t)__cvta_generic_to_shared(Ws);
    // A addr = as_base + (r*64 + wm*16 + row_off)*144 + (kk + col_off)*2
    const uint32_t uA0 = as_base + (wm*16 + row_off)*144 + col_off*2;
    // B addr = ws_base + (ks*16 + row_off)*144 + (wn*32 + nb*16 + col_off)*2
    const uint32_t uB0 = ws_base + row_off*144 + (wn*32 + col_off)*2;

    for (int tile = blockIdx.x; tile < GEMM_TILES; tile += gridDim.x){
        const int base = tile*64;

        __syncthreads();   // previous tile's As/Hs readers done (also covers Ws init on tile 0)
        // stage A: 4 relations x 64 rows x 64 halves
        #pragma unroll
        for (int r = 0; r < 4; r++){
            const __half* A = (r==0) ? g_agg_ss : (r==1) ? g_agg_as : (r==2) ? g_agg_us : Asub;
            #pragma unroll
            for (int it = 0; it < 2; it++){
                int chunk = it*256 + tid;       // 512 chunks of 8 halves
                int m = chunk >> 3, c = chunk & 7;
                *(uint4*)(As + (r*64 + m)*72 + c*8) =
                    *(const uint4*)(A + ((size_t)(base + m))*64 + c*8);
            }
        }
        __syncthreads();

        float c0[4], c1[4], c2[4], c3[4];
        #pragma unroll
        for (int t = 0; t < 4; t++){ c0[t]=0.f; c1[t]=0.f; c2[t]=0.f; c3[t]=0.f; }

        #pragma unroll
        for (int ks = 0; ks < 16; ks++){
            const int r  = ks >> 2;
            const int kk = (ks & 3) << 4;
            uint32_t a0,a1,a2,a3;
            ldsm_x4(a0,a1,a2,a3, uA0 + r*9216 + kk*2);
            uint32_t b0,b1,b2,b3, b4,b5,b6,b7;
            ldsm_x4_t(b0,b1,b2,b3, uB0 + ks*2304);          // n-cols wn*32 .. +15
            ldsm_x4_t(b4,b5,b6,b7, uB0 + ks*2304 + 32);     // n-cols wn*32+16 .. +31
            mma16816(c0, a0,a1,a2,a3, b0,b1);
            mma16816(c1, a0,a1,a2,a3, b2,b3);
            mma16816(c2, a0,a1,a2,a3, b4,b5);
            mma16816(c3, a0,a1,a2,a3, b6,b7);
        }

        // epilogue: c[t][0,1] -> (row, col), (row, col+1); c[t][2,3] -> (row+8, ...)
        const int mrow = wm*16 + (lane >> 2);
        const int ncol = wn*32 + ((lane & 3) << 1);
        float* cc[4] = {c0, c1, c2, c3};
        if (!do_head){
            #pragma unroll
            for (int t = 0; t < 4; t++){
                int col = ncol + t*8;
                float bb0 = Bs[col], bb1 = Bs[col+1];
                __half2 h0 = __floats2half2_rn(fmaxf(cc[t][0]+bb0,0.f), fmaxf(cc[t][1]+bb1,0.f));
                __half2 h1 = __floats2half2_rn(fmaxf(cc[t][2]+bb0,0.f), fmaxf(cc[t][3]+bb1,0.f));
                *(__half2*)(outp + ((size_t)(base+mrow  ))*64 + col) = h0;
                *(__half2*)(outp + ((size_t)(base+mrow+8))*64 + col) = h1;
            }
        } else {
            float* Hs = (float*)As;            // 64 nodes x stride 68
            __syncthreads();                   // all warps done reading As
            #pragma unroll
            for (int t = 0; t < 4; t++){
                int col = ncol + t*8;
                float bb0 = Bs[col], bb1 = Bs[col+1];
                Hs[(mrow  )*68 + col  ] = fmaxf(cc[t][0]+bb0,0.f);
                Hs[(mrow  )*68 + col+1] = fmaxf(cc[t][1]+bb1,0.f);
                Hs[(mrow+8)*68 + col  ] = fmaxf(cc[t][2]+bb0,0.f);
                Hs[(mrow+8)*68 + col+1] = fmaxf(cc[t][3]+bb1,0.f);
            }
            __syncthreads();
            int node = tid >> 2, q = tid & 3;  // 4 threads per node, 16 k each
            const float* hrow = Hs + node*68 + q*16;
            float p[6];
            #pragma unroll
            for (int o = 0; o < 6; o++) p[o] = 0.f;
            #pragma unroll
            for (int k = 0; k < 16; k++){
                float xv = hrow[k];
                #pragma unroll
                for (int o = 0; o < 6; o++) p[o] += xv * Wfs[o*64 + q*16 + k];
            }
            #pragma unroll
            for (int s = 1; s < 4; s <<= 1){
                #pragma unroll
                for (int o = 0; o < 6; o++) p[o] += __shfl_xor_sync(0xffffffffu, p[o], s);
            }
            if (q == 0){
                float m = -1e30f;
                #pragma unroll
                for (int o = 0; o < 6; o++){ p[o] += bfs[o]; m = fmaxf(m, p[o]); }
                float ssum = 0.f;
                #pragma unroll
                for (int o = 0; o < 6; o++){ p[o] = expf(p[o] - m); ssum += p[o]; }
                float inv = 1.f/ssum;
                float* op = outhead + (size_t)(base + node)*6;
                #pragma unroll
                for (int o = 0; o < 6; o++) op[o] = p[o]*inv;
            }
            // loop-top __syncthreads() protects Hs before next tile's As staging
        }
    }
}

// ---------------- launch ----------------
extern "C" void kernel_launch(void* const* d_in, const int* in_sizes, int n_in,
                              void* d_out, int out_size)
{
    const float* x_sub   = (const float*)d_in[0];
    const float* x_agr   = (const float*)d_in[1];
    const float* x_urb   = (const float*)d_in[2];
    const float* Wl      = (const float*)d_in[3];
    const float* bl      = (const float*)d_in[4];
    const float* Wr      = (const float*)d_in[5];
    const float* Wf      = (const float*)d_in[6];
    const float* bf      = (const float*)d_in[7];
    const int*   e_ss    = (const int*)d_in[8];
    const int*   e_as_s  = (const int*)d_in[9];
    const int*   e_as_d  = (const int*)d_in[10];
    const int*   e_us    = (const int*)d_in[11];
    float* out = (float*)d_out;

    cudaFuncSetAttribute(k_gemm, cudaFuncAttributeMaxDynamicSharedMemorySize, GEMM_SMEM);

    k_init<<<512,256>>>(Wl, bl, Wr);
    k_convert<<<8192,256>>>(x_sub, x_agr, x_urb);

    k_count_all<<<8192,256>>>(e_ss + ESS, e_as_d, e_us + EUS);

    k_scan_local_all<<<3*NB,1024>>>();
    k_scan_part_all<<<3,256>>>();
    k_scan_add_all<<<3*NB,1024>>>();

    k_fill_all<<<8192,256>>>(e_ss, e_ss + ESS, e_as_s, e_as_d, e_us, e_us + EUS);

    // layer-invariant aggregations, separate launches for L2 locality
    k_gather_ext<<<25000,256>>>(1, 1);
    k_gather_ext<<<25000,256>>>(2, 2);

    // layer 0: sum aggregation, sub input = h_sub, out -> g_sub0
    k_gather_ext<<<25000,256>>>(0, 0);
    k_gemm<<<296,256,GEMM_SMEM>>>(0, 0, 0, nullptr, nullptr, nullptr, 0);
    // layer 1: mean aggregation, sub input = g_sub0, out -> g_sub1
    k_gather_ss<<<25000,256>>>(1);
    k_gemm<<<296,256,GEMM_SMEM>>>(1, 1, 1, nullptr, nullptr, nullptr, 0);
    // layer 2: mean aggregation, sub input = g_sub1, head fused -> d_out
    k_gather_ss<<<25000,256>>>(2);
    k_gemm<<<296,256,GEMM_SMEM>>>(2, 0, 2, Wf, bf, out, 1);
}